// round 11
// baseline (speedup 1.0000x reference)
#include <cuda_runtime.h>
#include <cuda_fp16.h>
#include <math.h>
#include <stdint.h>

#define N     8192
#define FIN   256
#define FOUT  128
#define ALPHA 0.2f
#define NSPLIT 4
#define CH    32
#define NCHUNK ((N / NSPLIT) / CH)   // 64 chunks per CTA
#define STAGES 4
#define ITILE 256                     // i-rows per CTA

#define APITCH 144                    // adj staged row pitch (bytes)
#define BPITCH 64                     // B staged row pitch (bytes)

// k_attn dynamic SMEM layout (bytes)
#define S2_OFF    0
#define S2_BYTES  ((N / NSPLIT) * 4)                    // 8192
#define STG_BYTES (ITILE * APITCH + 128 * BPITCH)       // 36864 + 8192 = 45056
#define ADJ_OFF(s) (S2_BYTES + (s) * STG_BYTES)
#define BT_OFF(s)  (S2_BYTES + (s) * STG_BYTES + ITILE * APITCH)
#define SMEM_DYN  (S2_BYTES + STAGES * STG_BYTES)       // 188416 B

#define WH_SMEM 65536                 // k_wh dynamic smem

// ---------------- scratch (device globals; no allocs allowed) ---------------
__device__ __align__(16) __half g_WhT[FOUT * N];  // [f][perm(j)], fp16
__device__ float g_s1[N];
__device__ float g_s2[N];
__device__ __align__(16) float g_pnum[NSPLIT][N * FOUT];
__device__ float g_pden[NSPLIT][N];

// ---------------- helpers ----------------------------------------------------
__device__ __forceinline__ int perm32(int w) {
    return (((w & 7) >> 1) << 3) | (((w >> 3) & 3) << 1) | (w & 1);
}
__device__ __forceinline__ int permj(int j) {
    return (j & ~31) | perm32(j & 31);
}
__device__ __forceinline__ uint32_t smem_u32(const void* p) {
    uint32_t a;
    asm("{ .reg .u64 t; cvta.to.shared.u64 t, %1; cvt.u32.u64 %0, t; }" : "=r"(a) : "l"(p));
    return a;
}
__device__ __forceinline__ void cp_async16(uint32_t sa, const void* g) {
    asm volatile("cp.async.cg.shared.global [%0], [%1], 16;" :: "r"(sa), "l"(g) : "memory");
}
#define CP_COMMIT() asm volatile("cp.async.commit_group;" ::: "memory")
#define CP_WAIT(n)  asm volatile("cp.async.wait_group %0;" :: "n"(n) : "memory")

__device__ __forceinline__ float wfun(float t, int ad) {
    float l = fmaxf(t, ALPHA * t);
    float e;
    asm("ex2.approx.f32 %0, %1;" : "=f"(e) : "f"(l * 1.4426950408889634f));
    return (ad > 0) ? e : 0.0f;
}
__device__ __forceinline__ uint32_t h2u(__half2 h) {
    return *reinterpret_cast<uint32_t*>(&h);
}
__device__ __forceinline__ void mma_f16(float* d, const uint32_t* a, uint32_t b0, uint32_t b1) {
    asm volatile(
        "mma.sync.aligned.m16n8k16.row.col.f32.f16.f16.f32 "
        "{%0,%1,%2,%3}, {%4,%5,%6,%7}, {%8,%9}, {%0,%1,%2,%3};"
        : "+f"(d[0]), "+f"(d[1]), "+f"(d[2]), "+f"(d[3])
        : "r"(a[0]), "r"(a[1]), "r"(a[2]), "r"(a[3]), "r"(b0), "r"(b1));
}

// ---------------------------------------------------------------------------
// Kernel 1: Wh = x @ W^T via fp16 MMA (unchanged R10 winner)
// ---------------------------------------------------------------------------
__global__ __launch_bounds__(128) void k_wh(const float* __restrict__ x,
                                            const float* __restrict__ W) {
    extern __shared__ __align__(16) char wsm[];
    const int tid  = threadIdx.x;
    const int lane = tid & 31;
    const int wid  = tid >> 5;
    const int i0   = blockIdx.x * 64;
    const int qr = lane >> 2, qc = lane & 3;
    const int warp_m = wid * 16;

    for (int rr = 0; rr < 32; rr++) {
        const int f = wid * 32 + rr;
        const float4* wrow = reinterpret_cast<const float4*>(W + f * FIN);
        #pragma unroll
        for (int it = 0; it < 2; it++) {
            float4 v = wrow[lane + it * 32];
            int k = (lane + it * 32) * 4;
            int blk = k >> 5;
            int w5 = k & 31;
            int c = (w5 >> 1) & 3, u = (w5 >> 3) & 1, s = (w5 >> 4) & 1;
            int p0 = c * 8 + s * 4 + u * 2;
            *(__half2*)(wsm + blk * 8192 + f * 64 + p0 * 2)      = __floats2half2_rn(v.x, v.y);
            *(__half2*)(wsm + blk * 8192 + f * 64 + p0 * 2 + 16) = __floats2half2_rn(v.z, v.w);
        }
    }
    __syncthreads();

    const float* xa = x + (size_t)(i0 + warp_m + qr) * FIN + 2 * qc;
    const float* xb = xa + 8 * FIN;

    float acc[16][4];
    #pragma unroll
    for (int nt = 0; nt < 16; nt++)
        #pragma unroll
        for (int q = 0; q < 4; q++) acc[nt][q] = 0.0f;

    float2 fa[4], fb[4];
    #pragma unroll
    for (int q = 0; q < 4; q++) {
        fa[q] = *(const float2*)(xa + q * 8);
        fb[q] = *(const float2*)(xb + q * 8);
    }

    #pragma unroll
    for (int blk = 0; blk < 8; blk++) {
        uint32_t af0[4], af1[4];
        af0[0] = h2u(__floats2half2_rn(fa[0].x, fa[0].y));
        af0[1] = h2u(__floats2half2_rn(fb[0].x, fb[0].y));
        af0[2] = h2u(__floats2half2_rn(fa[1].x, fa[1].y));
        af0[3] = h2u(__floats2half2_rn(fb[1].x, fb[1].y));
        af1[0] = h2u(__floats2half2_rn(fa[2].x, fa[2].y));
        af1[1] = h2u(__floats2half2_rn(fb[2].x, fb[2].y));
        af1[2] = h2u(__floats2half2_rn(fa[3].x, fa[3].y));
        af1[3] = h2u(__floats2half2_rn(fb[3].x, fb[3].y));
        if (blk + 1 < 8) {
            #pragma unroll
            for (int q = 0; q < 4; q++) {
                fa[q] = *(const float2*)(xa + (blk + 1) * 32 + q * 8);
                fb[q] = *(const float2*)(xb + (blk + 1) * 32 + q * 8);
            }
        }
        const char* bbase = wsm + blk * 8192 + qr * 64 + qc * 16;
        #pragma unroll
        for (int nt = 0; nt < 16; nt++) {
            uint4 bv = *reinterpret_cast<const uint4*>(bbase + nt * 512);
            mma_f16(acc[nt], af0, bv.x, bv.y);
            mma_f16(acc[nt], af1, bv.z, bv.w);
        }
    }
    __syncthreads();

    __half* tsm = reinterpret_cast<__half*>(wsm);
    #pragma unroll
    for (int nt = 0; nt < 16; nt++) {
        #pragma unroll
        for (int r2 = 0; r2 < 2; r2++) {
            int j = warp_m + qr + 8 * r2;
            int f = nt * 8 + 2 * qc;
            *(__half2*)(tsm + j * 136 + f) =
                __floats2half2_rn(acc[nt][2 * r2], acc[nt][2 * r2 + 1]);
        }
    }
    __syncthreads();

    {
        const int f = tid;
        uint32_t buf[32];
        #pragma unroll
        for (int p = 0; p < 64; p += 2) {
            int c = (p >> 3) & 3, s = (p >> 2) & 1, u = (p >> 1) & 1;
            int jj = (p & 32) + 16 * s + 8 * u + 2 * c;
            __half h0 = tsm[jj * 136 + f];
            __half h1 = tsm[(jj + 1) * 136 + f];
            buf[p >> 1] = h2u(__halves2half2(h0, h1));
        }
        uint4* dst = reinterpret_cast<uint4*>(g_WhT + (size_t)f * N + i0);
        const uint4* src = reinterpret_cast<const uint4*>(buf);
        #pragma unroll
        for (int q = 0; q < 8; q++) dst[q] = src[q];
    }
}

// ---------------------------------------------------------------------------
// Kernel 1b: s1/s2 from WhT (permuted columns, fp16 source)
// ---------------------------------------------------------------------------
__global__ __launch_bounds__(128) void k_s(const float* __restrict__ a) {
    const int r  = blockIdx.x * 128 + threadIdx.x;
    const int pr = permj(r);
    float a1 = 0.0f, a2 = 0.0f;
    #pragma unroll 8
    for (int f = 0; f < FOUT; f++) {
        float w = __half2float(g_WhT[(size_t)f * N + pr]);
        a1 = fmaf(w, __ldg(&a[f]), a1);
        a2 = fmaf(w, __ldg(&a[FOUT + f]), a2);
    }
    g_s1[r] = a1;
    g_s2[r] = a2;
}

// ---------------------------------------------------------------------------
// Kernel 2: attention GEMM. 8 warps, warp tile 32 x 128 (B reads amortized
// over 2 m-tiles), i-tile 256, occ 1, 4-stage cp.async ring.
// ---------------------------------------------------------------------------
__global__ __launch_bounds__(256, 1) void k_attn(const int* __restrict__ adj) {
    extern __shared__ char smem[];
    const uint32_t sb = smem_u32(smem);
    float* const s2s = reinterpret_cast<float*>(smem + S2_OFF);

    const int tid   = threadIdx.x;
    const int lane  = tid & 31;
    const int wid   = tid >> 5;
    const int i0    = blockIdx.x * ITILE;
    const int split = blockIdx.y;
    const int jbeg  = split * (N / NSPLIT);

    // persistent s2 tile (8 KB)
    {
        const float4* src = reinterpret_cast<const float4*>(g_s2 + jbeg);
        float4* dst = reinterpret_cast<float4*>(s2s);
        #pragma unroll
        for (int u = 0; u < (N / NSPLIT) / 4 / 256; u++)
            dst[tid + u * 256] = src[tid + u * 256];
    }

    // cp.async mappings
    const int a_row = tid >> 3;          // +32 per u, u<8 (adj rows)
    const int a_c   = tid & 7;
    const int b_f0  = tid >> 2;          // +64 per u, u<2 (B rows)
    const int b_c   = tid & 3;

    // MMA fragment mapping: warp owns rows [warp_m, warp_m+32)
    const int qr = lane >> 2;
    const int qc = lane & 3;
    const int warp_m = wid * 32;
    float s1v[4];
    #pragma unroll
    for (int r = 0; r < 4; r++) s1v[r] = g_s1[i0 + warp_m + qr + 8 * r];
    uint32_t rowo[4];
    #pragma unroll
    for (int r = 0; r < 4; r++) rowo[r] = (uint32_t)(warp_m + qr + 8 * r) * APITCH;

    float acc[2][16][4];
    #pragma unroll
    for (int mt = 0; mt < 2; mt++)
        #pragma unroll
        for (int nt = 0; nt < 16; nt++)
            #pragma unroll
            for (int q = 0; q < 4; q++) acc[mt][nt][q] = 0.0f;
    float ds[4] = {0.f, 0.f, 0.f, 0.f};

    // prologue: stage chunks 0..STAGES-2
    #pragma unroll
    for (int s = 0; s < STAGES - 1; s++) {
        const int j0 = jbeg + s * CH;
        #pragma unroll
        for (int u = 0; u < 8; u++) {
            int r = a_row + u * 32;
            cp_async16(sb + ADJ_OFF(s) + r * APITCH + a_c * 16,
                       adj + (size_t)(i0 + r) * N + j0 + a_c * 4);
        }
        #pragma unroll
        for (int u = 0; u < 2; u++) {
            int ff = b_f0 + u * 64;
            cp_async16(sb + BT_OFF(s) + ff * BPITCH + b_c * 16,
                       g_WhT + (size_t)ff * N + j0 + b_c * 8);
        }
        CP_COMMIT();
    }

    int st = 0, sp = STAGES - 1;
    for (int c = 0; c < NCHUNK; c++) {
        const char* ap = smem + ADJ_OFF(st);
        const char* bp = smem + BT_OFF(st);

        CP_WAIT(STAGES - 2);
        __syncthreads();

        if (c + STAGES - 1 < NCHUNK) {
            const int jn = jbeg + (c + STAGES - 1) * CH;
            #pragma unroll
            for (int u = 0; u < 8; u++) {
                int r = a_row + u * 32;
                cp_async16(sb + ADJ_OFF(sp) + r * APITCH + a_c * 16,
                           adj + (size_t)(i0 + r) * N + jn + a_c * 4);
            }
            #pragma unroll
            for (int u = 0; u < 2; u++) {
                int ff = b_f0 + u * 64;
                cp_async16(sb + BT_OFF(sp) + ff * BPITCH + b_c * 16,
                           g_WhT + (size_t)ff * N + jn + b_c * 8);
            }
            CP_COMMIT();
        } else {
            CP_COMMIT();
        }

        // ---- A fragments: 2 m-tiles x 2 k-steps, fp16-rounded ----
        uint32_t afu[2][2][4];     // [ks][mt][frag]
        const float* s2c = s2s + c * CH;
        #pragma unroll
        for (int ks = 0; ks < 2; ks++) {
            const int jo = ks * 16 + 2 * qc;
            float2 s2p0 = *(const float2*)(s2c + jo);
            float2 s2p1 = *(const float2*)(s2c + jo + 8);
            #pragma unroll
            for (int mt = 0; mt < 2; mt++) {
                int2 ad00 = *(const int2*)(ap + rowo[2 * mt]     + jo * 4);
                int2 ad10 = *(const int2*)(ap + rowo[2 * mt + 1] + jo * 4);
                int2 ad01 = *(const int2*)(ap + rowo[2 * mt]     + jo * 4 + 32);
                int2 ad11 = *(const int2*)(ap + rowo[2 * mt + 1] + jo * 4 + 32);
                float sA = s1v[2 * mt], sB = s1v[2 * mt + 1];
                float w00 = wfun(sA + s2p0.x, ad00.x), w01 = wfun(sA + s2p0.y, ad00.y);
                float w10 = wfun(sB + s2p0.x, ad10.x), w11 = wfun(sB + s2p0.y, ad10.y);
                float w02 = wfun(sA + s2p1.x, ad01.x), w03 = wfun(sA + s2p1.y, ad01.y);
                float w12 = wfun(sB + s2p1.x, ad11.x), w13 = wfun(sB + s2p1.y, ad11.y);
                __half2 h0 = __floats2half2_rn(w00, w01);
                __half2 h1 = __floats2half2_rn(w10, w11);
                __half2 h2 = __floats2half2_rn(w02, w03);
                __half2 h3 = __floats2half2_rn(w12, w13);
                // denominators use the SAME rounded values the MMA consumes
                ds[2 * mt]     += (__low2float(h0) + __high2float(h0)) +
                                  (__low2float(h2) + __high2float(h2));
                ds[2 * mt + 1] += (__low2float(h1) + __high2float(h1)) +
                                  (__low2float(h3) + __high2float(h3));
                afu[ks][mt][0] = h2u(h0);
                afu[ks][mt][1] = h2u(h1);
                afu[ks][mt][2] = h2u(h2);
                afu[ks][mt][3] = h2u(h3);
            }
        }

        // ---- MMA: one B LDS.128 feeds 4 MMAs (2 m-tiles x 2 k-steps) ----
        #pragma unroll
        for (int nt = 0; nt < 16; nt++) {
            const uint4 bv = *reinterpret_cast<const uint4*>(bp + (nt * 8 + qr) * BPITCH + qc * 16);
            mma_f16(acc[0][nt], afu[0][0], bv.x, bv.y);
            mma_f16(acc[1][nt], afu[0][1], bv.x, bv.y);
            mma_f16(acc[0][nt], afu[1][0], bv.z, bv.w);
            mma_f16(acc[1][nt], afu[1][1], bv.z, bv.w);
        }

        st = (st + 1 == STAGES) ? 0 : st + 1;
        sp = (sp + 1 == STAGES) ? 0 : sp + 1;
    }

    // ---- denominators: reduce the 4 qc partials per row ----
    #pragma unroll
    for (int r = 0; r < 4; r++) {
        ds[r] += __shfl_xor_sync(0xffffffffu, ds[r], 1);
        ds[r] += __shfl_xor_sync(0xffffffffu, ds[r], 2);
    }
    if (qc == 0) {
        #pragma unroll
        for (int r = 0; r < 4; r++)
            g_pden[split][i0 + warp_m + qr + 8 * r] = ds[r];
    }

    // ---- numerators ----
    float* pn = g_pnum[split];
    #pragma unroll
    for (int mt = 0; mt < 2; mt++) {
        const int row0 = i0 + warp_m + mt * 16 + qr;
        #pragma unroll
        for (int nt = 0; nt < 16; nt++) {
            const int col = nt * 8 + 2 * qc;
            *reinterpret_cast<float2*>(pn + (size_t)row0 * FOUT + col) =
                make_float2(acc[mt][nt][0], acc[mt][nt][1]);
            *reinterpret_cast<float2*>(pn + (size_t)(row0 + 8) * FOUT + col) =
                make_float2(acc[mt][nt][2], acc[mt][nt][3]);
        }
    }
}

// ---------------------------------------------------------------------------
// Kernel 3: combine splits, normalize, ELU (vectorized)
// ---------------------------------------------------------------------------
__global__ __launch_bounds__(256) void k_final(float* __restrict__ out) {
    const int v   = blockIdx.x * 256 + threadIdx.x;
    const int row = v >> 5;
    const float4* p0 = reinterpret_cast<const float4*>(g_pnum[0]);
    const float4* p1 = reinterpret_cast<const float4*>(g_pnum[1]);
    const float4* p2 = reinterpret_cast<const float4*>(g_pnum[2]);
    const float4* p3 = reinterpret_cast<const float4*>(g_pnum[3]);
    float4 n0 = p0[v], n1 = p1[v], n2 = p2[v], n3 = p3[v];
    float den = g_pden[0][row] + g_pden[1][row] + g_pden[2][row] + g_pden[3][row];
    float inv = 1.0f / den;
    float4 h;
    h.x = (n0.x + n1.x + n2.x + n3.x) * inv;
    h.y = (n0.y + n1.y + n2.y + n3.y) * inv;
    h.z = (n0.z + n1.z + n2.z + n3.z) * inv;
    h.w = (n0.w + n1.w + n2.w + n3.w) * inv;
    h.x = h.x > 0.0f ? h.x : expm1f(h.x);
    h.y = h.y > 0.0f ? h.y : expm1f(h.y);
    h.z = h.z > 0.0f ? h.z : expm1f(h.z);
    h.w = h.w > 0.0f ? h.w : expm1f(h.w);
    reinterpret_cast<float4*>(out)[v] = h;
}

// ---------------------------------------------------------------------------
extern "C" void kernel_launch(void* const* d_in, const int* in_sizes, int n_in,
                              void* d_out, int out_size) {
    const float* x   = (const float*)d_in[0];
    const int*   adj = (const int*)  d_in[1];
    const float* W   = (const float*)d_in[2];
    const float* a   = (const float*)d_in[3];
    float* out = (float*)d_out;

    cudaFuncSetAttribute(k_wh,   cudaFuncAttributeMaxDynamicSharedMemorySize, WH_SMEM);
    cudaFuncSetAttribute(k_attn, cudaFuncAttributeMaxDynamicSharedMemorySize, SMEM_DYN);

    k_wh<<<N / 64, 128, WH_SMEM>>>(x, W);
    k_s<<<N / 128, 128>>>(a);
    dim3 g2(N / ITILE, NSPLIT);
    k_attn<<<g2, 256, SMEM_DYN>>>(adj);
    k_final<<<(N * FOUT) / 1024, 256>>>(out);
}

// round 12
// speedup vs baseline: 1.1370x; 1.1370x over previous
#include <cuda_runtime.h>
#include <cuda_fp16.h>
#include <math.h>
#include <stdint.h>

#define N     8192
#define FIN   256
#define FOUT  128
#define ALPHA 0.2f
#define LOG2E 1.4426950408889634f
#define NSPLIT 4
#define CH    32
#define NCHUNK ((N / NSPLIT) / CH)   // 64 chunks per CTA
#define STAGES 4

#define APITCH 144                    // adj staged row pitch (bytes)
#define BPITCH 64                     // B staged row pitch (bytes)

// k_attn dynamic SMEM layout (bytes)
#define S2_OFF    0
#define S2_BYTES  ((N / NSPLIT) * 4)                 // 8192
#define STG_BYTES (128 * APITCH + 128 * BPITCH)      // 26624
#define ADJ_OFF(s) (S2_BYTES + (s) * STG_BYTES)
#define BT_OFF(s)  (S2_BYTES + (s) * STG_BYTES + 128 * APITCH)
#define SMEM_DYN  (S2_BYTES + STAGES * STG_BYTES)    // 114688 B

#define WH_SMEM 65536                 // k_wh dynamic smem

// ---------------- scratch (device globals; no allocs allowed) ---------------
__device__ __align__(16) __half g_WhT[FOUT * N];  // [f][perm(j)], fp16
__device__ float g_s1[N];                          // prescaled by log2e
__device__ float g_s2[N];                          // prescaled by log2e
__device__ __align__(16) float g_pnum[NSPLIT][N * FOUT];
__device__ float g_pden[NSPLIT][N];

// ---------------- helpers ----------------------------------------------------
__device__ __forceinline__ int perm32(int w) {
    return (((w & 7) >> 1) << 3) | (((w >> 3) & 3) << 1) | (w & 1);
}
__device__ __forceinline__ uint32_t smem_u32(const void* p) {
    uint32_t a;
    asm("{ .reg .u64 t; cvta.to.shared.u64 t, %1; cvt.u32.u64 %0, t; }" : "=r"(a) : "l"(p));
    return a;
}
__device__ __forceinline__ void cp_async16(uint32_t sa, const void* g) {
    asm volatile("cp.async.cg.shared.global [%0], [%1], 16;" :: "r"(sa), "l"(g) : "memory");
}
#define CP_COMMIT() asm volatile("cp.async.commit_group;" ::: "memory")
#define CP_WAIT(n)  asm volatile("cp.async.wait_group %0;" :: "n"(n) : "memory")

// input t is prescaled by log2e; leaky-relu commutes with positive scaling
__device__ __forceinline__ float wfun(float t, int ad) {
    float l = fmaxf(t, ALPHA * t);
    float e;
    asm("ex2.approx.f32 %0, %1;" : "=f"(e) : "f"(l));
    return (ad > 0) ? e : 0.0f;
}
__device__ __forceinline__ uint32_t h2u(__half2 h) {
    return *reinterpret_cast<uint32_t*>(&h);
}
__device__ __forceinline__ void mma_f16(float* d, const uint32_t* a, uint32_t b0, uint32_t b1) {
    asm volatile(
        "mma.sync.aligned.m16n8k16.row.col.f32.f16.f16.f32 "
        "{%0,%1,%2,%3}, {%4,%5,%6,%7}, {%8,%9}, {%0,%1,%2,%3};"
        : "+f"(d[0]), "+f"(d[1]), "+f"(d[2]), "+f"(d[3])
        : "r"(a[0]), "r"(a[1]), "r"(a[2]), "r"(a[3]), "r"(b0), "r"(b1));
}

// ---------------------------------------------------------------------------
// Kernel 1: Wh = x @ W^T via fp16 MMA; fused s1/s2 (prescaled by log2e).
// ---------------------------------------------------------------------------
__global__ __launch_bounds__(128) void k_wh(const float* __restrict__ x,
                                            const float* __restrict__ W,
                                            const float* __restrict__ a) {
    extern __shared__ __align__(16) char wsm[];
    const int tid  = threadIdx.x;
    const int lane = tid & 31;
    const int wid  = tid >> 5;
    const int i0   = blockIdx.x * 64;
    const int qr = lane >> 2, qc = lane & 3;
    const int warp_m = wid * 16;

    // ---- W -> SMEM (fp16, B-perm) ----
    for (int rr = 0; rr < 32; rr++) {
        const int f = wid * 32 + rr;
        const float4* wrow = reinterpret_cast<const float4*>(W + f * FIN);
        #pragma unroll
        for (int it = 0; it < 2; it++) {
            float4 v = wrow[lane + it * 32];
            int k = (lane + it * 32) * 4;
            int blk = k >> 5;
            int w5 = k & 31;
            int c = (w5 >> 1) & 3, u = (w5 >> 3) & 1, s = (w5 >> 4) & 1;
            int p0 = c * 8 + s * 4 + u * 2;
            *(__half2*)(wsm + blk * 8192 + f * 64 + p0 * 2)      = __floats2half2_rn(v.x, v.y);
            *(__half2*)(wsm + blk * 8192 + f * 64 + p0 * 2 + 16) = __floats2half2_rn(v.z, v.w);
        }
    }
    __syncthreads();

    const float* xa = x + (size_t)(i0 + warp_m + qr) * FIN + 2 * qc;
    const float* xb = xa + 8 * FIN;

    float acc[16][4];
    #pragma unroll
    for (int nt = 0; nt < 16; nt++)
        #pragma unroll
        for (int q = 0; q < 4; q++) acc[nt][q] = 0.0f;

    float2 fa[4], fb[4];
    #pragma unroll
    for (int q = 0; q < 4; q++) {
        fa[q] = *(const float2*)(xa + q * 8);
        fb[q] = *(const float2*)(xb + q * 8);
    }

    #pragma unroll
    for (int blk = 0; blk < 8; blk++) {
        uint32_t af0[4], af1[4];
        af0[0] = h2u(__floats2half2_rn(fa[0].x, fa[0].y));
        af0[1] = h2u(__floats2half2_rn(fb[0].x, fb[0].y));
        af0[2] = h2u(__floats2half2_rn(fa[1].x, fa[1].y));
        af0[3] = h2u(__floats2half2_rn(fb[1].x, fb[1].y));
        af1[0] = h2u(__floats2half2_rn(fa[2].x, fa[2].y));
        af1[1] = h2u(__floats2half2_rn(fb[2].x, fb[2].y));
        af1[2] = h2u(__floats2half2_rn(fa[3].x, fa[3].y));
        af1[3] = h2u(__floats2half2_rn(fb[3].x, fb[3].y));
        if (blk + 1 < 8) {
            #pragma unroll
            for (int q = 0; q < 4; q++) {
                fa[q] = *(const float2*)(xa + (blk + 1) * 32 + q * 8);
                fb[q] = *(const float2*)(xb + (blk + 1) * 32 + q * 8);
            }
        }
        const char* bbase = wsm + blk * 8192 + qr * 64 + qc * 16;
        #pragma unroll
        for (int nt = 0; nt < 16; nt++) {
            uint4 bv = *reinterpret_cast<const uint4*>(bbase + nt * 512);
            mma_f16(acc[nt], af0, bv.x, bv.y);
            mma_f16(acc[nt], af1, bv.z, bv.w);
        }
    }
    __syncthreads();

    // ---- stage fp16 transpose tile [local j][136-half pitch] ----
    __half* tsm = reinterpret_cast<__half*>(wsm);
    #pragma unroll
    for (int nt = 0; nt < 16; nt++) {
        #pragma unroll
        for (int r2 = 0; r2 < 2; r2++) {
            int j = warp_m + qr + 8 * r2;
            int f = nt * 8 + 2 * qc;
            *(__half2*)(tsm + j * 136 + f) =
                __floats2half2_rn(acc[nt][2 * r2], acc[nt][2 * r2 + 1]);
        }
    }
    __syncthreads();

    // ---- coalesced permuted store ----
    {
        const int f = tid;
        uint32_t buf[32];
        #pragma unroll
        for (int p = 0; p < 64; p += 2) {
            int c = (p >> 3) & 3, s = (p >> 2) & 1, u = (p >> 1) & 1;
            int jj = (p & 32) + 16 * s + 8 * u + 2 * c;
            __half h0 = tsm[jj * 136 + f];
            __half h1 = tsm[(jj + 1) * 136 + f];
            buf[p >> 1] = h2u(__halves2half2(h0, h1));
        }
        uint4* dst = reinterpret_cast<uint4*>(g_WhT + (size_t)f * N + i0);
        const uint4* src = reinterpret_cast<const uint4*>(buf);
        #pragma unroll
        for (int q = 0; q < 8; q++) dst[q] = src[q];
    }

    // ---- fused s1/s2 from tsm (identical fp16 values k_s consumed) ----
    if (tid < 64) {
        const __half* row = tsm + tid * 136;
        float p1 = 0.0f, p2 = 0.0f;
        #pragma unroll 8
        for (int f = 0; f < FOUT; f += 2) {
            float2 w = __half22float2(*(const __half2*)(row + f));
            float2 a1 = *(const float2*)(a + f);
            float2 a2 = *(const float2*)(a + FOUT + f);
            p1 = fmaf(w.x, a1.x, p1); p1 = fmaf(w.y, a1.y, p1);
            p2 = fmaf(w.x, a2.x, p2); p2 = fmaf(w.y, a2.y, p2);
        }
        g_s1[i0 + tid] = p1 * LOG2E;
        g_s2[i0 + tid] = p2 * LOG2E;
    }
}

// ---------------------------------------------------------------------------
// Kernel 2: attention GEMM (R10 champion + prescale + fp32 denominators).
// ---------------------------------------------------------------------------
__global__ __launch_bounds__(256, 2) void k_attn(const int* __restrict__ adj) {
    extern __shared__ char smem[];
    const uint32_t sb = smem_u32(smem);
    float* const s2s = reinterpret_cast<float*>(smem + S2_OFF);

    const int tid   = threadIdx.x;
    const int lane  = tid & 31;
    const int wid   = tid >> 5;
    const int i0    = blockIdx.x * 128;
    const int split = blockIdx.y;
    const int jbeg  = split * (N / NSPLIT);

    {
        const float4* src = reinterpret_cast<const float4*>(g_s2 + jbeg);
        float4* dst = reinterpret_cast<float4*>(s2s);
        #pragma unroll
        for (int u = 0; u < (N / NSPLIT) / 4 / 256; u++)
            dst[tid + u * 256] = src[tid + u * 256];
    }

    const int a_row = tid >> 3;
    const int a_c   = tid & 7;
    const int b_f0  = tid >> 2;
    const int b_c   = tid & 3;

    const int qr = lane >> 2;
    const int qc = lane & 3;
    const int warp_m = wid * 16;
    const float s1a = g_s1[i0 + warp_m + qr];
    const float s1b = g_s1[i0 + warp_m + qr + 8];
    const uint32_t rowa = (uint32_t)(warp_m + qr) * APITCH;
    const uint32_t rowb = rowa + 8 * APITCH;

    float acc[16][4];
    #pragma unroll
    for (int nt = 0; nt < 16; nt++)
        #pragma unroll
        for (int q = 0; q < 4; q++) acc[nt][q] = 0.0f;
    float dsa = 0.f, dsb = 0.f;

    #pragma unroll
    for (int s = 0; s < STAGES - 1; s++) {
        const int j0 = jbeg + s * CH;
        #pragma unroll
        for (int u = 0; u < 4; u++) {
            int r = a_row + u * 32;
            cp_async16(sb + ADJ_OFF(s) + r * APITCH + a_c * 16,
                       adj + (size_t)(i0 + r) * N + j0 + a_c * 4);
        }
        #pragma unroll
        for (int u = 0; u < 2; u++) {
            int ff = b_f0 + u * 64;
            cp_async16(sb + BT_OFF(s) + ff * BPITCH + b_c * 16,
                       g_WhT + (size_t)ff * N + j0 + b_c * 8);
        }
        CP_COMMIT();
    }

    int st = 0, sp = STAGES - 1;
    for (int c = 0; c < NCHUNK; c++) {
        const char* ap = smem + ADJ_OFF(st);
        const char* bp = smem + BT_OFF(st);

        CP_WAIT(STAGES - 2);
        __syncthreads();

        if (c + STAGES - 1 < NCHUNK) {
            const int jn = jbeg + (c + STAGES - 1) * CH;
            #pragma unroll
            for (int u = 0; u < 4; u++) {
                int r = a_row + u * 32;
                cp_async16(sb + ADJ_OFF(sp) + r * APITCH + a_c * 16,
                           adj + (size_t)(i0 + r) * N + jn + a_c * 4);
            }
            #pragma unroll
            for (int u = 0; u < 2; u++) {
                int ff = b_f0 + u * 64;
                cp_async16(sb + BT_OFF(sp) + ff * BPITCH + b_c * 16,
                           g_WhT + (size_t)ff * N + jn + b_c * 8);
            }
            CP_COMMIT();
        } else {
            CP_COMMIT();
        }

        uint32_t afu[2][4];
        const float* s2c = s2s + c * CH;
        #pragma unroll
        for (int ks = 0; ks < 2; ks++) {
            const int jo = ks * 16 + 2 * qc;
            int2 ada0 = *(const int2*)(ap + rowa + jo * 4);
            int2 adb0 = *(const int2*)(ap + rowb + jo * 4);
            int2 ada1 = *(const int2*)(ap + rowa + jo * 4 + 32);
            int2 adb1 = *(const int2*)(ap + rowb + jo * 4 + 32);
            float2 s2p0 = *(const float2*)(s2c + jo);
            float2 s2p1 = *(const float2*)(s2c + jo + 8);
            float w00 = wfun(s1a + s2p0.x, ada0.x), w01 = wfun(s1a + s2p0.y, ada0.y);
            float w10 = wfun(s1b + s2p0.x, adb0.x), w11 = wfun(s1b + s2p0.y, adb0.y);
            float w02 = wfun(s1a + s2p1.x, ada1.x), w03 = wfun(s1a + s2p1.y, ada1.y);
            float w12 = wfun(s1b + s2p1.x, adb1.x), w13 = wfun(s1b + s2p1.y, adb1.y);
            // denominators in fp32 (den shift vs fp16 num weights ~4e-6, negligible)
            dsa += (w00 + w01) + (w02 + w03);
            dsb += (w10 + w11) + (w12 + w13);
            afu[ks][0] = h2u(__floats2half2_rn(w00, w01));
            afu[ks][1] = h2u(__floats2half2_rn(w10, w11));
            afu[ks][2] = h2u(__floats2half2_rn(w02, w03));
            afu[ks][3] = h2u(__floats2half2_rn(w12, w13));
        }

        #pragma unroll
        for (int nt = 0; nt < 16; nt++) {
            const uint4 bv = *reinterpret_cast<const uint4*>(bp + (nt * 8 + qr) * BPITCH + qc * 16);
            mma_f16(acc[nt], afu[0], bv.x, bv.y);
            mma_f16(acc[nt], afu[1], bv.z, bv.w);
        }

        st = (st + 1 == STAGES) ? 0 : st + 1;
        sp = (sp + 1 == STAGES) ? 0 : sp + 1;
    }

    dsa += __shfl_xor_sync(0xffffffffu, dsa, 1);
    dsa += __shfl_xor_sync(0xffffffffu, dsa, 2);
    dsb += __shfl_xor_sync(0xffffffffu, dsb, 1);
    dsb += __shfl_xor_sync(0xffffffffu, dsb, 2);
    if (qc == 0) {
        g_pden[split][i0 + warp_m + qr]     = dsa;
        g_pden[split][i0 + warp_m + qr + 8] = dsb;
    }

    float* pn = g_pnum[split];
    const int row0 = i0 + warp_m + qr;
    #pragma unroll
    for (int nt = 0; nt < 16; nt++) {
        const int col = nt * 8 + 2 * qc;
        *reinterpret_cast<float2*>(pn + (size_t)row0 * FOUT + col) =
            make_float2(acc[nt][0], acc[nt][1]);
        *reinterpret_cast<float2*>(pn + (size_t)(row0 + 8) * FOUT + col) =
            make_float2(acc[nt][2], acc[nt][3]);
    }
}

// ---------------------------------------------------------------------------
// Kernel 3: combine splits, normalize, ELU (vectorized)
// ---------------------------------------------------------------------------
__global__ __launch_bounds__(256) void k_final(float* __restrict__ out) {
    const int v   = blockIdx.x * 256 + threadIdx.x;
    const int row = v >> 5;
    const float4* p0 = reinterpret_cast<const float4*>(g_pnum[0]);
    const float4* p1 = reinterpret_cast<const float4*>(g_pnum[1]);
    const float4* p2 = reinterpret_cast<const float4*>(g_pnum[2]);
    const float4* p3 = reinterpret_cast<const float4*>(g_pnum[3]);
    float4 n0 = p0[v], n1 = p1[v], n2 = p2[v], n3 = p3[v];
    float den = g_pden[0][row] + g_pden[1][row] + g_pden[2][row] + g_pden[3][row];
    float inv = 1.0f / den;
    float4 h;
    h.x = (n0.x + n1.x + n2.x + n3.x) * inv;
    h.y = (n0.y + n1.y + n2.y + n3.y) * inv;
    h.z = (n0.z + n1.z + n2.z + n3.z) * inv;
    h.w = (n0.w + n1.w + n2.w + n3.w) * inv;
    h.x = h.x > 0.0f ? h.x : expm1f(h.x);
    h.y = h.y > 0.0f ? h.y : expm1f(h.y);
    h.z = h.z > 0.0f ? h.z : expm1f(h.z);
    h.w = h.w > 0.0f ? h.w : expm1f(h.w);
    reinterpret_cast<float4*>(out)[v] = h;
}

// ---------------------------------------------------------------------------
extern "C" void kernel_launch(void* const* d_in, const int* in_sizes, int n_in,
                              void* d_out, int out_size) {
    const float* x   = (const float*)d_in[0];
    const int*   adj = (const int*)  d_in[1];
    const float* W   = (const float*)d_in[2];
    const float* a   = (const float*)d_in[3];
    float* out = (float*)d_out;

    cudaFuncSetAttribute(k_wh,   cudaFuncAttributeMaxDynamicSharedMemorySize, WH_SMEM);
    cudaFuncSetAttribute(k_attn, cudaFuncAttributeMaxDynamicSharedMemorySize, SMEM_DYN);

    k_wh<<<N / 64, 128, WH_SMEM>>>(x, W, a);
    dim3 g2(N / 128, NSPLIT);
    k_attn<<<g2, 256, SMEM_DYN>>>(adj);
    k_final<<<(N * FOUT) / 1024, 256>>>(out);
}

// round 13
// speedup vs baseline: 1.1566x; 1.0172x over previous
#include <cuda_runtime.h>
#include <cuda_fp16.h>
#include <math.h>
#include <stdint.h>

#define N     8192
#define FIN   256
#define FOUT  128
#define ALPHA 0.2f
#define LOG2E 1.4426950408889634f
#define NSPLIT 4
#define CH    32
#define NCHUNK ((N / NSPLIT) / CH)   // 64 chunks per CTA
#define STAGES 4

#define APITCH 144                    // adj staged row pitch (bytes)
#define BPITCH 64                     // B staged row pitch (bytes)

// k_attn dynamic SMEM layout (bytes)
#define S2_OFF    0
#define S2_BYTES  ((N / NSPLIT) * 4)                 // 8192
#define STG_BYTES (128 * APITCH + 128 * BPITCH)      // 26624
#define ADJ_OFF(s) (S2_BYTES + (s) * STG_BYTES)
#define BT_OFF(s)  (S2_BYTES + (s) * STG_BYTES + 128 * APITCH)
#define SMEM_DYN  (S2_BYTES + STAGES * STG_BYTES)    // 114688 B

#define WH_SMEM 65536                 // k_wh dynamic smem

// ---------------- scratch (device globals; no allocs allowed) ---------------
__device__ __align__(16) __half g_WhT[FOUT * N];  // [f][perm(j)], fp16
__device__ float g_s1[N];                          // prescaled by log2e
__device__ float g_s2[N];                          // prescaled by log2e
__device__ __align__(16) float g_pnum[NSPLIT][N * FOUT];
__device__ float g_pden[NSPLIT][N];

// ---------------- helpers ----------------------------------------------------
__device__ __forceinline__ int perm32(int w) {
    return (((w & 7) >> 1) << 3) | (((w >> 3) & 3) << 1) | (w & 1);
}
__device__ __forceinline__ uint32_t smem_u32(const void* p) {
    uint32_t a;
    asm("{ .reg .u64 t; cvta.to.shared.u64 t, %1; cvt.u32.u64 %0, t; }" : "=r"(a) : "l"(p));
    return a;
}
__device__ __forceinline__ void cp_async16(uint32_t sa, const void* g) {
    asm volatile("cp.async.cg.shared.global [%0], [%1], 16;" :: "r"(sa), "l"(g) : "memory");
}
#define CP_COMMIT() asm volatile("cp.async.commit_group;" ::: "memory")
#define CP_WAIT(n)  asm volatile("cp.async.wait_group %0;" :: "n"(n) : "memory")

// input t is prescaled by log2e; leaky-relu commutes with positive scaling
__device__ __forceinline__ float wfun(float t, int ad) {
    float l = fmaxf(t, ALPHA * t);
    float e;
    asm("ex2.approx.f32 %0, %1;" : "=f"(e) : "f"(l));
    return (ad > 0) ? e : 0.0f;
}
__device__ __forceinline__ uint32_t h2u(__half2 h) {
    return *reinterpret_cast<uint32_t*>(&h);
}
__device__ __forceinline__ void mma_f16(float* d, const uint32_t* a, uint32_t b0, uint32_t b1) {
    asm volatile(
        "mma.sync.aligned.m16n8k16.row.col.f32.f16.f16.f32 "
        "{%0,%1,%2,%3}, {%4,%5,%6,%7}, {%8,%9}, {%0,%1,%2,%3};"
        : "+f"(d[0]), "+f"(d[1]), "+f"(d[2]), "+f"(d[3])
        : "r"(a[0]), "r"(a[1]), "r"(a[2]), "r"(a[3]), "r"(b0), "r"(b1));
}

// ---------------------------------------------------------------------------
// Kernel 1: Wh = x @ W^T via fp16 MMA; 8 warps (f-split pairs); fused s1/s2.
// ---------------------------------------------------------------------------
__global__ __launch_bounds__(256) void k_wh(const float* __restrict__ x,
                                            const float* __restrict__ W,
                                            const float* __restrict__ a) {
    extern __shared__ __align__(16) char wsm[];
    const int tid  = threadIdx.x;
    const int lane = tid & 31;
    const int wid  = tid >> 5;
    const int i0   = blockIdx.x * 64;
    const int qr = lane >> 2, qc = lane & 3;
    const int warp_m = (wid & 3) * 16;      // j-rows this warp computes
    const int ntbase = (wid >> 2) * 8;      // f-half this warp computes

    // ---- W -> SMEM (fp16, B-perm); 8 warps x 16 f-rows each ----
    for (int rr = 0; rr < 16; rr++) {
        const int f = wid * 16 + rr;
        const float4* wrow = reinterpret_cast<const float4*>(W + f * FIN);
        #pragma unroll
        for (int it = 0; it < 2; it++) {
            float4 v = wrow[lane + it * 32];
            int k = (lane + it * 32) * 4;
            int blk = k >> 5;
            int w5 = k & 31;
            int c = (w5 >> 1) & 3, u = (w5 >> 3) & 1, s = (w5 >> 4) & 1;
            int p0 = c * 8 + s * 4 + u * 2;
            *(__half2*)(wsm + blk * 8192 + f * 64 + p0 * 2)      = __floats2half2_rn(v.x, v.y);
            *(__half2*)(wsm + blk * 8192 + f * 64 + p0 * 2 + 16) = __floats2half2_rn(v.z, v.w);
        }
    }
    __syncthreads();

    const float* xa = x + (size_t)(i0 + warp_m + qr) * FIN + 2 * qc;
    const float* xb = xa + 8 * FIN;

    float acc[8][4];
    #pragma unroll
    for (int nt = 0; nt < 8; nt++)
        #pragma unroll
        for (int q = 0; q < 4; q++) acc[nt][q] = 0.0f;

    float2 fa[4], fb[4];
    #pragma unroll
    for (int q = 0; q < 4; q++) {
        fa[q] = *(const float2*)(xa + q * 8);
        fb[q] = *(const float2*)(xb + q * 8);
    }

    #pragma unroll
    for (int blk = 0; blk < 8; blk++) {
        uint32_t af0[4], af1[4];
        af0[0] = h2u(__floats2half2_rn(fa[0].x, fa[0].y));
        af0[1] = h2u(__floats2half2_rn(fb[0].x, fb[0].y));
        af0[2] = h2u(__floats2half2_rn(fa[1].x, fa[1].y));
        af0[3] = h2u(__floats2half2_rn(fb[1].x, fb[1].y));
        af1[0] = h2u(__floats2half2_rn(fa[2].x, fa[2].y));
        af1[1] = h2u(__floats2half2_rn(fb[2].x, fb[2].y));
        af1[2] = h2u(__floats2half2_rn(fa[3].x, fa[3].y));
        af1[3] = h2u(__floats2half2_rn(fb[3].x, fb[3].y));
        if (blk + 1 < 8) {
            #pragma unroll
            for (int q = 0; q < 4; q++) {
                fa[q] = *(const float2*)(xa + (blk + 1) * 32 + q * 8);
                fb[q] = *(const float2*)(xb + (blk + 1) * 32 + q * 8);
            }
        }
        const char* bbase = wsm + blk * 8192 + qr * 64 + qc * 16 + ntbase * 512;
        #pragma unroll
        for (int nt = 0; nt < 8; nt++) {
            uint4 bv = *reinterpret_cast<const uint4*>(bbase + nt * 512);
            mma_f16(acc[nt], af0, bv.x, bv.y);
            mma_f16(acc[nt], af1, bv.z, bv.w);
        }
    }
    __syncthreads();

    // ---- stage fp16 transpose tile [local j][136-half pitch] ----
    __half* tsm = reinterpret_cast<__half*>(wsm);
    #pragma unroll
    for (int nt = 0; nt < 8; nt++) {
        #pragma unroll
        for (int r2 = 0; r2 < 2; r2++) {
            int j = warp_m + qr + 8 * r2;
            int f = (ntbase + nt) * 8 + 2 * qc;
            *(__half2*)(tsm + j * 136 + f) =
                __floats2half2_rn(acc[nt][2 * r2], acc[nt][2 * r2 + 1]);
        }
    }
    __syncthreads();

    // ---- coalesced permuted store: 256 threads, each half an f-row ----
    {
        const int f    = tid & 127;
        const int half = tid >> 7;              // p-range [32*half, 32*half+32)
        uint32_t buf[16];
        #pragma unroll
        for (int pp = 0; pp < 32; pp += 2) {
            int p = half * 32 + pp;
            int c = (p >> 3) & 3, s = (p >> 2) & 1, u = (p >> 1) & 1;
            int jj = (p & 32) + 16 * s + 8 * u + 2 * c;
            __half h0 = tsm[jj * 136 + f];
            __half h1 = tsm[(jj + 1) * 136 + f];
            buf[pp >> 1] = h2u(__halves2half2(h0, h1));
        }
        uint4* dst = reinterpret_cast<uint4*>(g_WhT + (size_t)f * N + i0) + half * 4;
        const uint4* src = reinterpret_cast<const uint4*>(buf);
        #pragma unroll
        for (int q = 0; q < 4; q++) dst[q] = src[q];
    }

    // ---- fused s1/s2 from tsm (identical fp16 values) ----
    if (tid < 64) {
        const __half* row = tsm + tid * 136;
        float p1 = 0.0f, p2 = 0.0f;
        #pragma unroll 8
        for (int f = 0; f < FOUT; f += 2) {
            float2 w = __half22float2(*(const __half2*)(row + f));
            float2 a1 = *(const float2*)(a + f);
            float2 a2 = *(const float2*)(a + FOUT + f);
            p1 = fmaf(w.x, a1.x, p1); p1 = fmaf(w.y, a1.y, p1);
            p2 = fmaf(w.x, a2.x, p2); p2 = fmaf(w.y, a2.y, p2);
        }
        g_s1[i0 + tid] = p1 * LOG2E;
        g_s2[i0 + tid] = p2 * LOG2E;
    }
}

// ---------------------------------------------------------------------------
// Kernel 2: attention GEMM (R12 champion, unchanged)
// ---------------------------------------------------------------------------
__global__ __launch_bounds__(256, 2) void k_attn(const int* __restrict__ adj) {
    extern __shared__ char smem[];
    const uint32_t sb = smem_u32(smem);
    float* const s2s = reinterpret_cast<float*>(smem + S2_OFF);

    const int tid   = threadIdx.x;
    const int lane  = tid & 31;
    const int wid   = tid >> 5;
    const int i0    = blockIdx.x * 128;
    const int split = blockIdx.y;
    const int jbeg  = split * (N / NSPLIT);

    {
        const float4* src = reinterpret_cast<const float4*>(g_s2 + jbeg);
        float4* dst = reinterpret_cast<float4*>(s2s);
        #pragma unroll
        for (int u = 0; u < (N / NSPLIT) / 4 / 256; u++)
            dst[tid + u * 256] = src[tid + u * 256];
    }

    const int a_row = tid >> 3;
    const int a_c   = tid & 7;
    const int b_f0  = tid >> 2;
    const int b_c   = tid & 3;

    const int qr = lane >> 2;
    const int qc = lane & 3;
    const int warp_m = wid * 16;
    const float s1a = g_s1[i0 + warp_m + qr];
    const float s1b = g_s1[i0 + warp_m + qr + 8];
    const uint32_t rowa = (uint32_t)(warp_m + qr) * APITCH;
    const uint32_t rowb = rowa + 8 * APITCH;

    float acc[16][4];
    #pragma unroll
    for (int nt = 0; nt < 16; nt++)
        #pragma unroll
        for (int q = 0; q < 4; q++) acc[nt][q] = 0.0f;
    float dsa = 0.f, dsb = 0.f;

    #pragma unroll
    for (int s = 0; s < STAGES - 1; s++) {
        const int j0 = jbeg + s * CH;
        #pragma unroll
        for (int u = 0; u < 4; u++) {
            int r = a_row + u * 32;
            cp_async16(sb + ADJ_OFF(s) + r * APITCH + a_c * 16,
                       adj + (size_t)(i0 + r) * N + j0 + a_c * 4);
        }
        #pragma unroll
        for (int u = 0; u < 2; u++) {
            int ff = b_f0 + u * 64;
            cp_async16(sb + BT_OFF(s) + ff * BPITCH + b_c * 16,
                       g_WhT + (size_t)ff * N + j0 + b_c * 8);
        }
        CP_COMMIT();
    }

    int st = 0, sp = STAGES - 1;
    for (int c = 0; c < NCHUNK; c++) {
        const char* ap = smem + ADJ_OFF(st);
        const char* bp = smem + BT_OFF(st);

        CP_WAIT(STAGES - 2);
        __syncthreads();

        if (c + STAGES - 1 < NCHUNK) {
            const int jn = jbeg + (c + STAGES - 1) * CH;
            #pragma unroll
            for (int u = 0; u < 4; u++) {
                int r = a_row + u * 32;
                cp_async16(sb + ADJ_OFF(sp) + r * APITCH + a_c * 16,
                           adj + (size_t)(i0 + r) * N + jn + a_c * 4);
            }
            #pragma unroll
            for (int u = 0; u < 2; u++) {
                int ff = b_f0 + u * 64;
                cp_async16(sb + BT_OFF(sp) + ff * BPITCH + b_c * 16,
                           g_WhT + (size_t)ff * N + jn + b_c * 8);
            }
            CP_COMMIT();
        } else {
            CP_COMMIT();
        }

        uint32_t afu[2][4];
        const float* s2c = s2s + c * CH;
        #pragma unroll
        for (int ks = 0; ks < 2; ks++) {
            const int jo = ks * 16 + 2 * qc;
            int2 ada0 = *(const int2*)(ap + rowa + jo * 4);
            int2 adb0 = *(const int2*)(ap + rowb + jo * 4);
            int2 ada1 = *(const int2*)(ap + rowa + jo * 4 + 32);
            int2 adb1 = *(const int2*)(ap + rowb + jo * 4 + 32);
            float2 s2p0 = *(const float2*)(s2c + jo);
            float2 s2p1 = *(const float2*)(s2c + jo + 8);
            float w00 = wfun(s1a + s2p0.x, ada0.x), w01 = wfun(s1a + s2p0.y, ada0.y);
            float w10 = wfun(s1b + s2p0.x, adb0.x), w11 = wfun(s1b + s2p0.y, adb0.y);
            float w02 = wfun(s1a + s2p1.x, ada1.x), w03 = wfun(s1a + s2p1.y, ada1.y);
            float w12 = wfun(s1b + s2p1.x, adb1.x), w13 = wfun(s1b + s2p1.y, adb1.y);
            dsa += (w00 + w01) + (w02 + w03);
            dsb += (w10 + w11) + (w12 + w13);
            afu[ks][0] = h2u(__floats2half2_rn(w00, w01));
            afu[ks][1] = h2u(__floats2half2_rn(w10, w11));
            afu[ks][2] = h2u(__floats2half2_rn(w02, w03));
            afu[ks][3] = h2u(__floats2half2_rn(w12, w13));
        }

        #pragma unroll
        for (int nt = 0; nt < 16; nt++) {
            const uint4 bv = *reinterpret_cast<const uint4*>(bp + (nt * 8 + qr) * BPITCH + qc * 16);
            mma_f16(acc[nt], afu[0], bv.x, bv.y);
            mma_f16(acc[nt], afu[1], bv.z, bv.w);
        }

        st = (st + 1 == STAGES) ? 0 : st + 1;
        sp = (sp + 1 == STAGES) ? 0 : sp + 1;
    }

    dsa += __shfl_xor_sync(0xffffffffu, dsa, 1);
    dsa += __shfl_xor_sync(0xffffffffu, dsa, 2);
    dsb += __shfl_xor_sync(0xffffffffu, dsb, 1);
    dsb += __shfl_xor_sync(0xffffffffu, dsb, 2);
    if (qc == 0) {
        g_pden[split][i0 + warp_m + qr]     = dsa;
        g_pden[split][i0 + warp_m + qr + 8] = dsb;
    }

    float* pn = g_pnum[split];
    const int row0 = i0 + warp_m + qr;
    #pragma unroll
    for (int nt = 0; nt < 16; nt++) {
        const int col = nt * 8 + 2 * qc;
        *reinterpret_cast<float2*>(pn + (size_t)row0 * FOUT + col) =
            make_float2(acc[nt][0], acc[nt][1]);
        *reinterpret_cast<float2*>(pn + (size_t)(row0 + 8) * FOUT + col) =
            make_float2(acc[nt][2], acc[nt][3]);
    }
}

// ---------------------------------------------------------------------------
// Kernel 3: combine splits, normalize, ELU (vectorized)
// ---------------------------------------------------------------------------
__global__ __launch_bounds__(256) void k_final(float* __restrict__ out) {
    const int v   = blockIdx.x * 256 + threadIdx.x;
    const int row = v >> 5;
    const float4* p0 = reinterpret_cast<const float4*>(g_pnum[0]);
    const float4* p1 = reinterpret_cast<const float4*>(g_pnum[1]);
    const float4* p2 = reinterpret_cast<const float4*>(g_pnum[2]);
    const float4* p3 = reinterpret_cast<const float4*>(g_pnum[3]);
    float4 n0 = p0[v], n1 = p1[v], n2 = p2[v], n3 = p3[v];
    float den = g_pden[0][row] + g_pden[1][row] + g_pden[2][row] + g_pden[3][row];
    float inv = 1.0f / den;
    float4 h;
    h.x = (n0.x + n1.x + n2.x + n3.x) * inv;
    h.y = (n0.y + n1.y + n2.y + n3.y) * inv;
    h.z = (n0.z + n1.z + n2.z + n3.z) * inv;
    h.w = (n0.w + n1.w + n2.w + n3.w) * inv;
    h.x = h.x > 0.0f ? h.x : expm1f(h.x);
    h.y = h.y > 0.0f ? h.y : expm1f(h.y);
    h.z = h.z > 0.0f ? h.z : expm1f(h.z);
    h.w = h.w > 0.0f ? h.w : expm1f(h.w);
    reinterpret_cast<float4*>(out)[v] = h;
}

// ---------------------------------------------------------------------------
extern "C" void kernel_launch(void* const* d_in, const int* in_sizes, int n_in,
                              void* d_out, int out_size) {
    const float* x   = (const float*)d_in[0];
    const int*   adj = (const int*)  d_in[1];
    const float* W   = (const float*)d_in[2];
    const float* a   = (const float*)d_in[3];
    float* out = (float*)d_out;

    cudaFuncSetAttribute(k_wh,   cudaFuncAttributeMaxDynamicSharedMemorySize, WH_SMEM);
    cudaFuncSetAttribute(k_attn, cudaFuncAttributeMaxDynamicSharedMemorySize, SMEM_DYN);

    k_wh<<<N / 64, 256, WH_SMEM>>>(x, W, a);
    dim3 g2(N / 128, NSPLIT);
    k_attn<<<g2, 256, SMEM_DYN>>>(adj);
    k_final<<<(N * FOUT) / 1024, 256>>>(out);
}